// round 17
// baseline (speedup 1.0000x reference)
#include <cuda_runtime.h>
#include <cuda_fp16.h>
#include <cstdint>

#define NN 50000
#define EE 800000
#define TOT (NN + EE)
#define GG 128
#define DH 128
#define SCAN_B 1024
#define NSB ((NN + SCAN_B - 1) / SCAN_B)   // 49
#define KPAD1 304                           // 300 padded to 16
#define KPAD2 128

// ---------------- scratch (static device globals; no allocation) ----------------
__device__ __align__(16) __half g_A[(size_t)NN * DH];  // GEMM output (fp16)
__device__ __align__(16) __half g_Bh[(size_t)NN * DH]; // layer-1 agg output (fp16)
__device__ float  g_AS[NN];
__device__ float  g_AD[NN];
__device__ int    g_counts[NN];
__device__ int    g_rowptr[NN + 1];
__device__ int    g_off[NN];
__device__ int    g_csr[TOT];
__device__ int    g_bsum[NSB];
__device__ int    g_boff[NSB];
__device__ float  g_gsum[GG * DH];
__device__ float  g_gcnt[GG];
__device__ int    g_posIsByte;
// transposed fp16 weights: [n=128][kpad]
__device__ __align__(16) __half g_Wt1[128 * KPAD1];
__device__ __align__(16) __half g_Wt2[128 * KPAD2];

// ---------------- utility ----------------
__device__ __forceinline__ float gelu_exact(float x) {
    return 0.5f * x * (1.0f + erff(x * 0.70710678118654752f));
}

__device__ __forceinline__ void mma16816h(float* c, const uint32_t* a,
                                          uint32_t b0, uint32_t b1) {
    asm volatile(
        "mma.sync.aligned.m16n8k16.row.col.f32.f16.f16.f32 "
        "{%0,%1,%2,%3}, {%4,%5,%6,%7}, {%8,%9}, {%0,%1,%2,%3};"
        : "+f"(c[0]), "+f"(c[1]), "+f"(c[2]), "+f"(c[3])
        : "r"(a[0]), "r"(a[1]), "r"(a[2]), "r"(a[3]), "r"(b0), "r"(b1));
}

__device__ __forceinline__ uint32_t packh2(float2 v) {
    __half2 h = __float22half2_rn(v);
    return *(uint32_t*)&h;
}

// ---------------- zero scratch accumulators ----------------
__global__ void zero_k() {
    int i = blockIdx.x * blockDim.x + threadIdx.x;
    if (i < NN) g_counts[i] = 0;
    if (i < GG * DH) g_gsum[i] = 0.f;
    if (i < GG) g_gcnt[i] = 0.f;
}

// ---------------- detect pos dtype (bool bytes vs int32) ----------------
__global__ void detect_pos_k(const unsigned char* __restrict__ pos) {
    __shared__ int any;
    if (threadIdx.x == 0) any = 0;
    __syncthreads();
    int found = 0;
    for (int i = threadIdx.x; i < 4096; i += blockDim.x) {
        if ((i & 3) != 0 && pos[i] != 0) found = 1;
    }
    if (found) atomicOr(&any, 1);
    __syncthreads();
    if (threadIdx.x == 0) g_posIsByte = any;
}

// ---------------- weight transpose fp16: W[K][128] -> Wt[128][Kpad] ----------------
__global__ void wconv_k(const float* __restrict__ W, int K, int Kpad,
                        __half* __restrict__ o) {
    int idx = blockIdx.x * blockDim.x + threadIdx.x;
    if (idx >= 128 * Kpad) return;
    int k = idx >> 7;
    int n = idx & 127;
    float v = (k < K) ? W[k * 128 + n] : 0.f;
    o[n * Kpad + k] = __float2half_rn(v);
}

// ---------------- CSR build ----------------
__global__ void count_k(const int* __restrict__ ei) {
    int i = blockIdx.x * blockDim.x + threadIdx.x;
    if (i >= TOT) return;
    int d = (i < EE) ? ei[EE + i] : (i - EE);
    atomicAdd(&g_counts[d], 1);
}

__global__ void scan1_k() {
    int t = threadIdx.x;
    int i = blockIdx.x * SCAN_B + t;
    int v = (i < NN) ? g_counts[i] : 0;
#pragma unroll
    for (int o = 16; o; o >>= 1) v += __shfl_down_sync(0xffffffffu, v, o);
    __shared__ int ws[32];
    if ((t & 31) == 0) ws[t >> 5] = v;
    __syncthreads();
    if (t < 32) {
        int s = ws[t];
#pragma unroll
        for (int o = 16; o; o >>= 1) s += __shfl_down_sync(0xffffffffu, s, o);
        if (t == 0) g_bsum[blockIdx.x] = s;
    }
}

__global__ void scan2_k() {
    if (threadIdx.x == 0) {
        int run = 0;
        for (int b = 0; b < NSB; b++) { g_boff[b] = run; run += g_bsum[b]; }
        g_rowptr[0] = 0;
    }
}

__global__ void scan3_k() {
    int t = threadIdx.x, lane = t & 31, w = t >> 5;
    int i = blockIdx.x * SCAN_B + t;
    int v = (i < NN) ? g_counts[i] : 0;
    int incl = v;
#pragma unroll
    for (int o = 1; o < 32; o <<= 1) {
        int u = __shfl_up_sync(0xffffffffu, incl, o);
        if (lane >= o) incl += u;
    }
    __shared__ int ws[32];
    if (lane == 31) ws[w] = incl;
    __syncthreads();
    if (t < 32) {
        int s = ws[t];
#pragma unroll
        for (int o = 1; o < 32; o <<= 1) {
            int u = __shfl_up_sync(0xffffffffu, s, o);
            if (t >= o) s += u;
        }
        ws[t] = s;
    }
    __syncthreads();
    int blockIncl = incl + (w > 0 ? ws[w - 1] : 0);
    if (i < NN) {
        int r = blockIncl + g_boff[blockIdx.x];
        g_rowptr[i + 1] = r;
        g_off[i] = r - v;
    }
}

__global__ void scatter_k(const int* __restrict__ ei) {
    int i = blockIdx.x * blockDim.x + threadIdx.x;
    if (i >= TOT) return;
    int s, d;
    if (i < EE) { s = ei[i]; d = ei[EE + i]; }
    else        { s = d = i - EE; }
    int p = atomicAdd(&g_off[d], 1);
    g_csr[p] = s;
}

// ---------------- tensor GEMM (fp32 input) + fused att dots ----------------
__global__ void __launch_bounds__(256)
tgemm_k(const float* __restrict__ A, int M, int K, int Kc,
        const uint32_t* __restrict__ Wt, int Kpad2,
        const float* __restrict__ av, const float* __restrict__ bv) {
    __shared__ float    sA[128][16];
    __shared__ uint32_t sW[128 * 9];

    int tid = threadIdx.x;
    int w = tid >> 5, lane = tid & 31;
    int g = lane >> 2, tg = lane & 3;
    int m0 = blockIdx.x * 128;

    float c[64];
#pragma unroll
    for (int i = 0; i < 64; i++) c[i] = 0.f;

    float4 pfA[2];
    uint32_t pW[4];
    int aIdx0 = tid * 2;

    auto loadA = [&](int ch) {
#pragma unroll
        for (int i = 0; i < 2; i++) {
            int idx = aIdx0 + i;
            int row = idx >> 2, c4 = idx & 3;
            int m = m0 + row, k = ch * 16 + c4 * 4;
            if (m < M && k < K)
                pfA[i] = *(const float4*)(A + (size_t)m * K + k);
            else
                pfA[i] = make_float4(0.f, 0.f, 0.f, 0.f);
        }
    };
    auto loadW = [&](int ch) {
        int k02 = ch * 8;
#pragma unroll
        for (int i = 0; i < 4; i++) {
            int idx = tid + i * 256;
            int row = idx >> 3, cc = idx & 7;
            pW[i] = Wt[row * Kpad2 + k02 + cc];
        }
    };

    loadA(0); loadW(0);

    for (int ch = 0; ch < Kc; ch++) {
#pragma unroll
        for (int i = 0; i < 2; i++) {
            int idx = aIdx0 + i;
            int row = idx >> 2, c4 = idx & 3;
            *(float4*)&sA[row][c4 * 4] = pfA[i];
        }
#pragma unroll
        for (int i = 0; i < 4; i++) {
            int idx = tid + i * 256;
            int row = idx >> 3, cc = idx & 7;
            sW[row * 9 + cc] = pW[i];
        }
        __syncthreads();

        if (ch + 1 < Kc) { loadA(ch + 1); loadW(ch + 1); }

        int r = w * 16 + g;
        uint32_t a[4];
        a[0] = packh2(*(const float2*)&sA[r][tg * 2]);
        a[1] = packh2(*(const float2*)&sA[r + 8][tg * 2]);
        a[2] = packh2(*(const float2*)&sA[r][tg * 2 + 8]);
        a[3] = packh2(*(const float2*)&sA[r + 8][tg * 2 + 8]);

#pragma unroll
        for (int nt = 0; nt < 16; nt++) {
            int nrow = nt * 8 + g;
            uint32_t b0 = sW[nrow * 9 + tg];
            uint32_t b1 = sW[nrow * 9 + tg + 4];
            mma16816h(c + nt * 4, a, b0, b1);
        }
        __syncthreads();
    }

    int r0 = m0 + w * 16 + g, r1 = r0 + 8;
    float ss0 = 0.f, dd0 = 0.f, ss1 = 0.f, dd1 = 0.f;
#pragma unroll
    for (int nt = 0; nt < 16; nt++) {
        float2 a2 = *(const float2*)&av[nt * 8 + tg * 2];
        float2 b2 = *(const float2*)&bv[nt * 8 + tg * 2];
        float c0 = c[nt * 4], c1 = c[nt * 4 + 1], c2 = c[nt * 4 + 2], c3 = c[nt * 4 + 3];
        ss0 += c0 * a2.x + c1 * a2.y;  dd0 += c0 * b2.x + c1 * b2.y;
        ss1 += c2 * a2.x + c3 * a2.y;  dd1 += c2 * b2.x + c3 * b2.y;
        if (r0 < M) *(__half2*)&g_A[(size_t)r0 * DH + nt * 8 + tg * 2] = __floats2half2_rn(c0, c1);
        if (r1 < M) *(__half2*)&g_A[(size_t)r1 * DH + nt * 8 + tg * 2] = __floats2half2_rn(c2, c3);
    }
    ss0 += __shfl_xor_sync(0xffffffffu, ss0, 1); ss0 += __shfl_xor_sync(0xffffffffu, ss0, 2);
    dd0 += __shfl_xor_sync(0xffffffffu, dd0, 1); dd0 += __shfl_xor_sync(0xffffffffu, dd0, 2);
    ss1 += __shfl_xor_sync(0xffffffffu, ss1, 1); ss1 += __shfl_xor_sync(0xffffffffu, ss1, 2);
    dd1 += __shfl_xor_sync(0xffffffffu, dd1, 1); dd1 += __shfl_xor_sync(0xffffffffu, dd1, 2);
    if (tg == 0) {
        if (r0 < M) { g_AS[r0] = ss0; g_AD[r0] = dd0; }
        if (r1 < M) { g_AS[r1] = ss1; g_AD[r1] = dd1; }
    }
}

// ---------------- tensor GEMM (fp16 input, K=128) + fused att dots ----------------
__global__ void __launch_bounds__(256)
tgemm_h_k(const __half* __restrict__ A, int M, int Kc,
          const uint32_t* __restrict__ Wt, int Kpad2,
          const float* __restrict__ av, const float* __restrict__ bv) {
    __shared__ uint32_t sAh[128][12];
    __shared__ uint32_t sW[128 * 9];

    int tid = threadIdx.x;
    int w = tid >> 5, lane = tid & 31;
    int g = lane >> 2, tg = lane & 3;
    int m0 = blockIdx.x * 128;

    float c[64];
#pragma unroll
    for (int i = 0; i < 64; i++) c[i] = 0.f;

    uint4 pfA;
    uint32_t pW[4];
    int aRow = tid >> 1, aCol = (tid & 1) * 4;

    auto loadA = [&](int ch) {
        int m = m0 + aRow;
        if (m < M)
            pfA = *(const uint4*)((const uint32_t*)(A + (size_t)m * DH) + ch * 8 + aCol);
        else
            pfA = make_uint4(0, 0, 0, 0);
    };
    auto loadW = [&](int ch) {
        int k02 = ch * 8;
#pragma unroll
        for (int i = 0; i < 4; i++) {
            int idx = tid + i * 256;
            int row = idx >> 3, cc = idx & 7;
            pW[i] = Wt[row * Kpad2 + k02 + cc];
        }
    };

    loadA(0); loadW(0);

    for (int ch = 0; ch < Kc; ch++) {
        *(uint4*)&sAh[aRow][aCol] = pfA;
#pragma unroll
        for (int i = 0; i < 4; i++) {
            int idx = tid + i * 256;
            int row = idx >> 3, cc = idx & 7;
            sW[row * 9 + cc] = pW[i];
        }
        __syncthreads();

        if (ch + 1 < Kc) { loadA(ch + 1); loadW(ch + 1); }

        int r = w * 16 + g;
        uint32_t a[4];
        a[0] = sAh[r][tg];
        a[1] = sAh[r + 8][tg];
        a[2] = sAh[r][tg + 4];
        a[3] = sAh[r + 8][tg + 4];

#pragma unroll
        for (int nt = 0; nt < 16; nt++) {
            int nrow = nt * 8 + g;
            uint32_t b0 = sW[nrow * 9 + tg];
            uint32_t b1 = sW[nrow * 9 + tg + 4];
            mma16816h(c + nt * 4, a, b0, b1);
        }
        __syncthreads();
    }

    int r0 = m0 + w * 16 + g, r1 = r0 + 8;
    float ss0 = 0.f, dd0 = 0.f, ss1 = 0.f, dd1 = 0.f;
#pragma unroll
    for (int nt = 0; nt < 16; nt++) {
        float2 a2 = *(const float2*)&av[nt * 8 + tg * 2];
        float2 b2 = *(const float2*)&bv[nt * 8 + tg * 2];
        float c0 = c[nt * 4], c1 = c[nt * 4 + 1], c2 = c[nt * 4 + 2], c3 = c[nt * 4 + 3];
        ss0 += c0 * a2.x + c1 * a2.y;  dd0 += c0 * b2.x + c1 * b2.y;
        ss1 += c2 * a2.x + c3 * a2.y;  dd1 += c2 * b2.x + c3 * b2.y;
        if (r0 < M) *(__half2*)&g_A[(size_t)r0 * DH + nt * 8 + tg * 2] = __floats2half2_rn(c0, c1);
        if (r1 < M) *(__half2*)&g_A[(size_t)r1 * DH + nt * 8 + tg * 2] = __floats2half2_rn(c2, c3);
    }
    ss0 += __shfl_xor_sync(0xffffffffu, ss0, 1); ss0 += __shfl_xor_sync(0xffffffffu, ss0, 2);
    dd0 += __shfl_xor_sync(0xffffffffu, dd0, 1); dd0 += __shfl_xor_sync(0xffffffffu, dd0, 2);
    ss1 += __shfl_xor_sync(0xffffffffu, ss1, 1); ss1 += __shfl_xor_sync(0xffffffffu, ss1, 2);
    dd1 += __shfl_xor_sync(0xffffffffu, dd1, 1); dd1 += __shfl_xor_sync(0xffffffffu, dd1, 2);
    if (tg == 0) {
        if (r0 < M) { g_AS[r0] = ss0; g_AD[r0] = dd0; }
        if (r1 < M) { g_AS[r1] = ss1; g_AD[r1] = dd1; }
    }
}

// ---------------- GAT aggregation: one WARP per dst, single pass, strip x8 ----------------
// Strip-mined x8: 8 independent LDG.64 in flight per batch to halve latency exposures.
__global__ void agg_k(const float* __restrict__ bias, int mode,
                      const int* __restrict__ batch, const void* __restrict__ posv) {
    int wid = (blockIdx.x * blockDim.x + threadIdx.x) >> 5;
    if (wid >= NN) return;
    int lane = threadIdx.x & 31;
    int n = wid;
    int beg = g_rowptr[n], end = g_rowptr[n + 1];
    float ad = g_AD[n];

    float4 acc = make_float4(0.f, 0.f, 0.f, 0.f);
    float s_l = 0.f;
    const __half* __restrict__ Abase = g_A + (size_t)lane * 4;

    auto fmaOne = [&](float wj, uint2 v) {
        float2 f01 = __half22float2(*(const __half2*)&v.x);
        float2 f23 = __half22float2(*(const __half2*)&v.y);
        acc.x = fmaf(wj, f01.x, acc.x);
        acc.y = fmaf(wj, f01.y, acc.y);
        acc.z = fmaf(wj, f23.x, acc.z);
        acc.w = fmaf(wj, f23.y, acc.w);
    };

    for (int c = beg; c < end; c += 32) {
        int e = c + lane;
        float w_l = 0.f;
        int src_l = 0;
        if (e < end) {
            src_l = g_csr[e];
            float ev = g_AS[src_l] + ad;
            ev = (ev > 0.f) ? ev : 0.2f * ev;
            w_l = __expf(ev);
        }
        s_l += w_l;
        int cnt = min(32, end - c);
        int j = 0;
        for (; j + 8 <= cnt; j += 8) {
            float wv[8]; int sv[8]; uint2 hv[8];
#pragma unroll
            for (int q = 0; q < 8; q++) {
                wv[q] = __shfl_sync(0xffffffffu, w_l, j + q);
                sv[q] = __shfl_sync(0xffffffffu, src_l, j + q);
            }
#pragma unroll
            for (int q = 0; q < 8; q++)
                hv[q] = *(const uint2*)(Abase + (size_t)sv[q] * DH);
#pragma unroll
            for (int q = 0; q < 8; q++)
                fmaOne(wv[q], hv[q]);
        }
        for (; j < cnt; j++) {
            float wj = __shfl_sync(0xffffffffu, w_l, j);
            int   sj = __shfl_sync(0xffffffffu, src_l, j);
            uint2 v = *(const uint2*)(Abase + (size_t)sj * DH);
            fmaOne(wj, v);
        }
    }
#pragma unroll
    for (int o = 16; o; o >>= 1) s_l += __shfl_xor_sync(0xffffffffu, s_l, o);
    float inv = 1.0f / s_l;

    float4 b4 = ((const float4*)bias)[lane];
    float4 r;
    r.x = acc.x * inv + b4.x;
    r.y = acc.y * inv + b4.y;
    r.z = acc.z * inv + b4.z;
    r.w = acc.w * inv + b4.w;

    if (mode == 0) {
        r.x = gelu_exact(r.x); r.y = gelu_exact(r.y);
        r.z = gelu_exact(r.z); r.w = gelu_exact(r.w);
        uint2 st;
        *(__half2*)&st.x = __floats2half2_rn(r.x, r.y);
        *(__half2*)&st.y = __floats2half2_rn(r.z, r.w);
        *(uint2*)(&g_Bh[(size_t)n * DH + lane * 4]) = st;
    } else {
        bool p;
        if (g_posIsByte) p = ((const unsigned char*)posv)[n] != 0;
        else             p = ((const int*)posv)[n] != 0;
        if (p) {
            int g = batch[n];
            float* dst = &g_gsum[(size_t)g * DH + lane * 4];
            atomicAdd(dst + 0, r.x);
            atomicAdd(dst + 1, r.y);
            atomicAdd(dst + 2, r.z);
            atomicAdd(dst + 3, r.w);
            if (lane == 0) atomicAdd(&g_gcnt[g], 1.0f);
        }
    }
}

// ---------------- finalize: logits + gelu + fc -> scores ----------------
__global__ void final_k(const float* __restrict__ Wfc, const float* __restrict__ bfc,
                        float* __restrict__ out, int score_off, int logit_off) {
    int g = blockIdx.x, t = threadIdx.x;
    float denom = fmaxf(g_gcnt[g], 1.0f);
    float l = g_gsum[(size_t)g * DH + t] / denom;
    if (logit_off >= 0) out[logit_off + g * DH + t] = l;
    float ge = gelu_exact(l);
    __shared__ float sh[DH];
    sh[t] = ge * Wfc[t];
    __syncthreads();
#pragma unroll
    for (int o = 64; o; o >>= 1) {
        if (t < o) sh[t] += sh[t + o];
        __syncthreads();
    }
    if (t == 0 && score_off >= 0) out[score_off + g] = sh[0] + bfc[0];
}

// ---------------- stream/event resources (created once; no device memory) ----------------
struct SideRes {
    cudaStream_t side;
    cudaEvent_t evFork, evJoin;
    SideRes() {
        cudaStreamCreateWithFlags(&side, cudaStreamNonBlocking);
        cudaEventCreateWithFlags(&evFork, cudaEventDisableTiming);
        cudaEventCreateWithFlags(&evJoin, cudaEventDisableTiming);
    }
};

// ---------------- launch ----------------
extern "C" void kernel_launch(void* const* d_in, const int* in_sizes, int n_in,
                              void* d_out, int out_size) {
    static SideRes R;

    int o = (n_in >= 15) ? 1 : 0;   // num_graphs scalar present?
    const float* x     = (const float*)d_in[0];
    const int*   ei    = (const int*)d_in[1];
    const int*   batch = (const int*)d_in[2];
    const void*  pos   = (const void*)d_in[3];
    const float* W1  = (const float*)d_in[4 + o];
    const float* as1 = (const float*)d_in[5 + o];
    const float* ad1 = (const float*)d_in[6 + o];
    const float* b1  = (const float*)d_in[7 + o];
    const float* W2  = (const float*)d_in[8 + o];
    const float* as2 = (const float*)d_in[9 + o];
    const float* ad2 = (const float*)d_in[10 + o];
    const float* b2  = (const float*)d_in[11 + o];
    const float* Wfc = (const float*)d_in[12 + o];
    const float* bfc = (const float*)d_in[13 + o];
    float* out = (float*)d_out;

    void *pBh, *pW1, *pW2;
    cudaGetSymbolAddress(&pBh, g_Bh);
    cudaGetSymbolAddress(&pW1, g_Wt1);
    cudaGetSymbolAddress(&pW2, g_Wt2);

    int score_off = 0, logit_off = 128;
    if (out_size == 16384)      { score_off = -1; logit_off = 0; }
    else if (out_size == 128)   { score_off = 0;  logit_off = -1; }

    // Fork: CSR build + zeroing + W2 conversion on side stream.
    cudaEventRecord(R.evFork, 0);
    cudaStreamWaitEvent(R.side, R.evFork, 0);

    zero_k<<<(NN + 255) / 256, 256, 0, R.side>>>();
    detect_pos_k<<<1, 256, 0, R.side>>>((const unsigned char*)pos);
    wconv_k<<<(128 * KPAD2 + 255) / 256, 256, 0, R.side>>>(W2, 128, KPAD2, (__half*)pW2);
    int eb = (TOT + 255) / 256;
    count_k<<<eb, 256, 0, R.side>>>(ei);
    scan1_k<<<NSB, SCAN_B, 0, R.side>>>();
    scan2_k<<<1, 32, 0, R.side>>>();
    scan3_k<<<NSB, SCAN_B, 0, R.side>>>();
    scatter_k<<<eb, 256, 0, R.side>>>(ei);
    cudaEventRecord(R.evJoin, R.side);

    // main stream: W1 convert, then tensor GEMM1 (+fused att dots)
    wconv_k<<<(128 * KPAD1 + 255) / 256, 256>>>(W1, 300, KPAD1, (__half*)pW1);
    tgemm_k<<<(NN + 127) / 128, 256>>>(x, NN, 300, KPAD1 / 16,
                                       (const uint32_t*)pW1, KPAD1 / 2, as1, ad1);

    // join: aggregation needs both H and CSR
    cudaStreamWaitEvent(0, R.evJoin, 0);
    agg_k<<<(NN * 32 + 255) / 256, 256>>>(b1, 0, batch, pos);

    // layer 2 (fp16-input GEMM reads g_Bh directly)
    tgemm_h_k<<<(NN + 127) / 128, 256>>>((const __half*)pBh, NN, KPAD2 / 16,
                                         (const uint32_t*)pW2, KPAD2 / 2, as2, ad2);
    agg_k<<<(NN * 32 + 255) / 256, 256>>>(b2, 1, batch, pos);

    // head
    final_k<<<GG, 128>>>(Wfc, bfc, out, score_off, logit_off);
}